// round 3
// baseline (speedup 1.0000x reference)
#include <cuda_runtime.h>
#include <math.h>

#define NPRI  10647
#define BB    16
#define LL    50
#define NCLS  80
#define BLKS_PER_B 42          // ceil(10647/256)

// ---------------- compile-time priors (double math -> f32, matches numpy) ----
struct alignas(16) Priors {
    float box[NPRI][4];   // px, py, pw, ph
    float aux[NPRI][4];   // col(j), row(i), aw_pix, ah_pix
};

constexpr Priors mk_priors() {
    Priors t{};
    const int AW[3][3] = {{116, 156, 373}, {30, 62, 59}, {10, 16, 33}};
    const int AH[3][3] = {{90, 198, 326}, {61, 45, 119}, {13, 30, 23}};
    const int SSv[3] = {13, 26, 52};
    int n = 0;
    for (int l = 0; l < 3; l++) {
        int S = SSv[l];
        for (int i = 0; i < S; i++)
            for (int j = 0; j < S; j++)
                for (int a = 0; a < 3; a++) {
                    double w = AW[l][a] / 416.0;
                    double h = AH[l][a] / 416.0;
                    double cx = (j + 0.5) / (double)S;
                    double cy = (i + 0.5) / (double)S;
                    t.box[n][0] = (float)(cx - 0.5 * w);
                    t.box[n][1] = (float)(cy - 0.5 * h);
                    t.box[n][2] = (float)w;
                    t.box[n][3] = (float)h;
                    t.aux[n][0] = (float)j;
                    t.aux[n][1] = (float)i;
                    t.aux[n][2] = (float)AW[l][a];
                    t.aux[n][3] = (float)AH[l][a];
                    n++;
                }
    }
    return t;
}
__device__ constexpr Priors g_P = mk_priors();

// ---------------- compact cross-kernel state (no dense arrays) ---------------
__device__ int   g_idx[BB * LL];       // chosen prior per (b,label), -1 invalid
__device__ float g_cls[BB * LL];
__device__ float g_tall[BB * LL][4];
__device__ float g_acc[9];             // [lvl*3 + {obj,coord,cls}]
__device__ int   g_done = 0;

// min(softplus(y),100) == clamped BCE term
__device__ __forceinline__ float bce_term(float y) {
    float sp = fmaxf(y, 0.0f) + __logf(1.0f + __expf(-fabsf(y)));
    return fminf(sp, 100.0f);
}

__device__ __forceinline__ float iou_f(float px, float py, float pw, float ph,
                                       float bx, float by, float bxe, float bye,
                                       float barea) {
    float ix = fmaxf(px, bx);
    float iy = fmaxf(py, by);
    float ax = fminf(__fadd_rn(px, pw), bxe);
    float ay = fminf(__fadd_rn(py, ph), bye);
    float inter = __fmul_rn(fmaxf(__fsub_rn(ax, ix), 0.0f),
                            fmaxf(__fsub_rn(ay, iy), 0.0f));
    float denom = __fsub_rn(__fadd_rn(__fmul_rn(pw, ph), barea), inter);
    return __fdiv_rn(inter, denom);
}

// ---------------------------------------------------------------- targets
// one block per (b,label); 256 threads; writes compact record
__global__ void __launch_bounds__(256) k_targets(const float* __restrict__ labels) {
    __shared__ float sious[NPRI];
    __shared__ float sred[256];
    __shared__ int   wsum[8];
    __shared__ int   woff[9];

    int gl  = blockIdx.x;
    int tid = threadIdx.x;
    int lane = tid & 31, wid = tid >> 5;

    if (gl == 0 && tid < 9) g_acc[tid] = 0.f;   // zero accumulators for this run

    const float* lab = labels + (size_t)gl * 5;
    float cls = lab[0];
    if (cls < 0.0f) {
        if (tid == 0) g_idx[gl] = -1;
        return;
    }
    float bx = lab[1], by = lab[2], bw = lab[3], bh = lab[4];
    float barea = __fmul_rn(bw, bh);
    float bxe = __fadd_rn(bx, bw);
    float bye = __fadd_rn(by, bh);

    // pass 1: iou into smem
    float lmax = -1e30f;
    for (int n = tid; n < NPRI; n += 256) {
        const float4 p = *(const float4*)g_P.box[n];
        float iou = iou_f(p.x, p.y, p.z, p.w, bx, by, bxe, bye, barea);
        sious[n] = iou;
        lmax = fmaxf(lmax, iou);
    }
    sred[tid] = lmax;
    __syncthreads();
    for (int s = 128; s > 0; s >>= 1) {
        if (tid < s) sred[tid] = fmaxf(sred[tid], sred[tid + s]);
        __syncthreads();
    }
    float m = sred[0];

    // pass 2: tie count in contiguous per-thread chunks (ordered)
    const int CH = 42;
    int start = tid * CH;
    int end = min(start + CH, NPRI);
    int cnt = 0;
    for (int n = start; n < end; n++)
        if (sious[n] == m) cnt++;

    // warp-level inclusive scan of cnt
    int inc = cnt;
    #pragma unroll
    for (int o = 1; o < 32; o <<= 1) {
        int v = __shfl_up_sync(0xffffffffu, inc, o);
        if (lane >= o) inc += v;
    }
    if (lane == 31) wsum[wid] = inc;
    __syncthreads();
    if (tid == 0) {
        int r = 0;
        #pragma unroll
        for (int w2 = 0; w2 < 8; w2++) { woff[w2] = r; r += wsum[w2]; }
        woff[8] = r;
    }
    __syncthreads();
    int excl = woff[wid] + inc - cnt;
    int k = woff[8];
    int rank = (k - 1) / 2 + 1;

    if (excl < rank && rank <= excl + cnt) {
        int need = rank - excl;
        int idx = -1;
        for (int n = start; n < end; n++)
            if (sious[n] == m && --need == 0) { idx = n; break; }
        const float* aux = g_P.aux[idx];
        float Sf = (idx < 507) ? 13.f : (idx < 2535) ? 26.f : 52.f;
        float dx = fminf(fmaxf((bx + 0.5f * bw) * Sf - aux[0], 1e-6f), 0.999999f);
        float dy = fminf(fmaxf((by + 0.5f * bh) * Sf - aux[1], 1e-6f), 0.999999f);
        g_tall[gl][0] = logf(dx / (1.0f - dx));
        g_tall[gl][1] = logf(dy / (1.0f - dy));
        g_tall[gl][2] = logf(bw * 416.0f / aux[2]);
        g_tall[gl][3] = logf(bh * 416.0f / aux[3]);
        g_cls[gl] = cls;
        g_idx[gl] = idx;
    }
}

// ---------------------------------------------------------------- loss (+final)
// grid = BB * BLKS_PER_B; block covers 256 priors of one batch
__global__ void __launch_bounds__(256) k_loss(const float* __restrict__ o0,
                                              const float* __restrict__ o1,
                                              const float* __restrict__ o2,
                                              const float* __restrict__ labels,
                                              float* __restrict__ outp) {
    __shared__ float sacc[9];
    __shared__ int   s_n;
    __shared__ float s_lab[LL][5];       // bx, by, bxe, bye, barea
    __shared__ int   s_idx[LL];
    __shared__ int   s_l[LL];
    __shared__ float s_cls[LL];
    __shared__ float s_tall[LL][4];
    __shared__ bool  s_last;

    int b     = blockIdx.x / BLKS_PER_B;
    int chunk = blockIdx.x % BLKS_PER_B;
    int tid   = threadIdx.x;

    if (tid < 9) sacc[tid] = 0.f;
    if (tid == 0) s_n = 0;
    __syncthreads();

    if (tid < LL) {
        int gl = b * LL + tid;
        int idx = g_idx[gl];
        if (idx >= 0) {
            int p = atomicAdd(&s_n, 1);
            const float* lab = labels + (size_t)gl * 5;
            float bx = lab[1], by = lab[2], bw = lab[3], bh = lab[4];
            s_lab[p][0] = bx;
            s_lab[p][1] = by;
            s_lab[p][2] = __fadd_rn(bx, bw);
            s_lab[p][3] = __fadd_rn(by, bh);
            s_lab[p][4] = __fmul_rn(bw, bh);
            s_idx[p] = idx;
            s_l[p]   = tid;
            s_cls[p] = g_cls[gl];
            s_tall[p][0] = g_tall[gl][0];
            s_tall[p][1] = g_tall[gl][1];
            s_tall[p][2] = g_tall[gl][2];
            s_tall[p][3] = g_tall[gl][3];
        }
    }
    __syncthreads();
    int V = s_n;

    int n = chunk * 256 + tid;
    bool active = n < NPRI;

    int lvl = 0, SS_ = 1;
    const float* base = nullptr;
    bool chosen = false, supp = false;
    int we = -1;
    unsigned m0 = 0, m1 = 0, m2 = 0;
    float objc = 0.f;

    if (active) {
        int off;
        const float* out;
        if (n < 507)       { lvl = 0; SS_ = 169;  off = 0;    out = o0; }
        else if (n < 2535) { lvl = 1; SS_ = 676;  off = 507;  out = o1; }
        else               { lvl = 2; SS_ = 2704; off = 2535; out = o2; }
        int rl = n - off;
        // prior n corresponds to (cell, a) with n = off + cell*3 + a
        int a = rl % 3;
        int cell = rl / 3;
        base = out + (size_t)b * 255 * SS_ + (size_t)a * 85 * SS_ + cell;

        const float4 p = *(const float4*)g_P.box[n];
        int wl = -1;
        for (int e = 0; e < V; e++) {
            float iou = iou_f(p.x, p.y, p.z, p.w,
                              s_lab[e][0], s_lab[e][1], s_lab[e][2],
                              s_lab[e][3], s_lab[e][4]);
            supp |= (iou >= 0.5f);
            if (s_idx[e] == n) {
                if (s_l[e] > wl) { wl = s_l[e]; we = e; }
                int ci = (int)s_cls[e];
                if (ci < 32)      m0 |= 1u << ci;
                else if (ci < 64) m1 |= 1u << (ci - 32);
                else              m2 |= 1u << (ci - 64);
            }
        }
        chosen = (we >= 0);
        bool om = chosen || !supp;
        if (om) {
            float x = base[4 * SS_];
            objc = bce_term(chosen ? -x : x);
        }
    }
    if (objc != 0.f) atomicAdd(&sacc[lvl * 3 + 0], objc);

    // warp-cooperative handling of chosen priors
    unsigned cmask = __ballot_sync(0xffffffffu, chosen);
    int myl = tid & 31;
    while (cmask) {
        int src = __ffs(cmask) - 1;
        cmask &= cmask - 1;
        unsigned long long bp = __shfl_sync(0xffffffffu, (unsigned long long)base, src);
        const float* cb = (const float*)bp;
        int cwe = __shfl_sync(0xffffffffu, we, src);
        int cS  = __shfl_sync(0xffffffffu, SS_, src);
        int cl  = __shfl_sync(0xffffffffu, lvl, src);
        unsigned cm0 = __shfl_sync(0xffffffffu, m0, src);
        unsigned cm1 = __shfl_sync(0xffffffffu, m1, src);
        unsigned cm2 = __shfl_sync(0xffffffffu, m2, src);

        float csum = 0.f;
        if (myl < 4) {
            float d = cb[myl * cS] - s_tall[cwe][myl];
            csum = d * d;
        }
        float ksum = 0.f;
        #pragma unroll
        for (int kb = 0; kb < 3; kb++) {
            int k = myl + kb * 32;
            if (k < NCLS) {
                float x = cb[(5 + k) * cS];
                unsigned mw = (k < 32) ? cm0 : (k < 64) ? cm1 : cm2;
                bool bit = (mw >> (k & 31)) & 1u;
                ksum += bce_term(bit ? -x : x);
            }
        }
        #pragma unroll
        for (int o = 16; o > 0; o >>= 1) {
            csum += __shfl_xor_sync(0xffffffffu, csum, o);
            ksum += __shfl_xor_sync(0xffffffffu, ksum, o);
        }
        if (myl == 0) {
            atomicAdd(&sacc[cl * 3 + 1], csum);
            atomicAdd(&sacc[cl * 3 + 2], ksum);
        }
    }

    __syncthreads();
    if (tid < 9 && sacc[tid] != 0.f) atomicAdd(&g_acc[tid], sacc[tid]);
    __threadfence();
    __syncthreads();
    if (tid == 0)
        s_last = (atomicAdd(&g_done, 1) == (int)gridDim.x - 1);
    __syncthreads();

    if (s_last && tid == 0) {
        volatile float* acc = g_acc;
        float obj = 0.f, crd = 0.f, cl = 0.f;
        const float ss[3] = {169.f, 676.f, 2704.f};
        #pragma unroll
        for (int l = 0; l < 3; l++) {
            obj += acc[l * 3 + 0] / (48.f * ss[l]);
            crd += acc[l * 3 + 1] / (192.f * ss[l]);
            cl  += acc[l * 3 + 2] / (3840.f * ss[l]);
        }
        outp[0] = obj;
        outp[1] = crd;
        outp[2] = cl;
        g_done = 0;   // reset for next graph replay
    }
}

// ---------------------------------------------------------------- launch
extern "C" void kernel_launch(void* const* d_in, const int* in_sizes, int n_in,
                              void* d_out, int out_size) {
    const float *o0 = nullptr, *o1 = nullptr, *o2 = nullptr, *lab = nullptr;
    for (int i = 0; i < n_in; i++) {
        switch (in_sizes[i]) {
            case 16 * 255 * 13 * 13: o0 = (const float*)d_in[i]; break;
            case 16 * 255 * 26 * 26: o1 = (const float*)d_in[i]; break;
            case 16 * 255 * 52 * 52: o2 = (const float*)d_in[i]; break;
            case 16 * 1 * 50 * 5:    lab = (const float*)d_in[i]; break;
            default: break;
        }
    }
    if (!o0 || !o1 || !o2 || !lab) {
        o0 = (const float*)d_in[0];
        o1 = (const float*)d_in[1];
        o2 = (const float*)d_in[2];
        lab = (const float*)d_in[3];
    }

    k_targets<<<BB * LL, 256>>>(lab);
    k_loss<<<BB * BLKS_PER_B, 256>>>(o0, o1, o2, lab, (float*)d_out);
}

// round 4
// speedup vs baseline: 1.0875x; 1.0875x over previous
#include <cuda_runtime.h>
#include <math.h>

#define NPRI  10647
#define BB    16
#define LL    50
#define NCLS  80
#define BLKS_PER_B 45      // lvl0: 3 blocks, lvl1: 9, lvl2: 33 (cell-contiguous per anchor)
#define SUPPW_PER_B 339    // 3*(6+22+85) words, segments padded per (lvl,a)

// ---------------- compile-time priors (double math -> f32, matches numpy) ----
struct alignas(16) Priors {
    float box[NPRI][4];   // px, py, pw, ph
    float aux[NPRI][4];   // col(j), row(i), aw_pix, ah_pix
};

constexpr Priors mk_priors() {
    Priors t{};
    const int AW[3][3] = {{116, 156, 373}, {30, 62, 59}, {10, 16, 33}};
    const int AH[3][3] = {{90, 198, 326}, {61, 45, 119}, {13, 30, 23}};
    const int SSv[3] = {13, 26, 52};
    int n = 0;
    for (int l = 0; l < 3; l++) {
        int S = SSv[l];
        for (int i = 0; i < S; i++)
            for (int j = 0; j < S; j++)
                for (int a = 0; a < 3; a++) {
                    double w = AW[l][a] / 416.0;
                    double h = AH[l][a] / 416.0;
                    double cx = (j + 0.5) / (double)S;
                    double cy = (i + 0.5) / (double)S;
                    t.box[n][0] = (float)(cx - 0.5 * w);
                    t.box[n][1] = (float)(cy - 0.5 * h);
                    t.box[n][2] = (float)w;
                    t.box[n][3] = (float)h;
                    t.aux[n][0] = (float)j;
                    t.aux[n][1] = (float)i;
                    t.aux[n][2] = (float)AW[l][a];
                    t.aux[n][3] = (float)AH[l][a];
                    n++;
                }
    }
    return t;
}
__device__ constexpr Priors g_P = mk_priors();

// ---------------- compact cross-kernel state -------------------------------
__device__ int      g_idx[BB * LL];            // chosen prior per (b,label), -1 invalid
__device__ float    g_cls[BB * LL];
__device__ float    g_tall[BB * LL][4];
__device__ unsigned g_suppw[BB * SUPPW_PER_B]; // supp bitmask; cleared by k_loss each run
__device__ float    g_acc[9];                  // [lvl*3 + {obj,coord,cls}]; reset by final blk
__device__ int      g_done = 0;

// word-segment base (within one batch) for (lvl, a)
__device__ __host__ __forceinline__ int seg_base(int lvl, int a) {
    return (lvl == 0) ? a * 6 : (lvl == 1) ? 18 + a * 22 : 84 + a * 85;
}

// min(softplus(y),100) == clamped BCE term
__device__ __forceinline__ float bce_term(float y) {
    float sp = fmaxf(y, 0.0f) + __logf(1.0f + __expf(-fabsf(y)));
    return fminf(sp, 100.0f);
}

__device__ __forceinline__ float iou_f(float px, float py, float pw, float ph,
                                       float bx, float by, float bxe, float bye,
                                       float barea) {
    float ix = fmaxf(px, bx);
    float iy = fmaxf(py, by);
    float ax = fminf(__fadd_rn(px, pw), bxe);
    float ay = fminf(__fadd_rn(py, ph), bye);
    float inter = __fmul_rn(fmaxf(__fsub_rn(ax, ix), 0.0f),
                            fmaxf(__fsub_rn(ay, iy), 0.0f));
    float denom = __fsub_rn(__fadd_rn(__fmul_rn(pw, ph), barea), inter);
    return __fdiv_rn(inter, denom);
}

__device__ __forceinline__ void decode_prior(int n, int& lvl, int& a, int& cell) {
    int rl;
    if (n < 507)       { lvl = 0; rl = n; }
    else if (n < 2535) { lvl = 1; rl = n - 507; }
    else               { lvl = 2; rl = n - 2535; }
    a = rl % 3;
    cell = rl / 3;
}

// ---------------------------------------------------------------- targets
// one block per (b,label); 256 threads; emits compact record + supp bits
__global__ void __launch_bounds__(256) k_targets(const float* __restrict__ labels) {
    __shared__ float sious[NPRI];
    __shared__ float sred[256];
    __shared__ int   wsum[8];
    __shared__ int   woff[9];

    int gl  = blockIdx.x;
    int b   = gl / LL;
    int tid = threadIdx.x;
    int lane = tid & 31, wid = tid >> 5;

    const float* lab = labels + (size_t)gl * 5;
    float cls = lab[0];
    if (cls < 0.0f) {
        if (tid == 0) g_idx[gl] = -1;
        return;
    }
    float bx = lab[1], by = lab[2], bw = lab[3], bh = lab[4];
    float barea = __fmul_rn(bw, bh);
    float bxe = __fadd_rn(bx, bw);
    float bye = __fadd_rn(by, bh);

    // pass 1: iou into smem; mark supp bits
    float lmax = -1e30f;
    for (int n = tid; n < NPRI; n += 256) {
        const float4 p = *(const float4*)g_P.box[n];
        float iou = iou_f(p.x, p.y, p.z, p.w, bx, by, bxe, bye, barea);
        sious[n] = iou;
        lmax = fmaxf(lmax, iou);
        if (iou >= 0.5f) {
            int lvl, a, cell;
            decode_prior(n, lvl, a, cell);
            atomicOr(&g_suppw[b * SUPPW_PER_B + seg_base(lvl, a) + (cell >> 5)],
                     1u << (cell & 31));
        }
    }
    sred[tid] = lmax;
    __syncthreads();
    for (int s = 128; s > 0; s >>= 1) {
        if (tid < s) sred[tid] = fmaxf(sred[tid], sred[tid + s]);
        __syncthreads();
    }
    float m = sred[0];

    // pass 2: tie count in contiguous per-thread chunks (ordered)
    const int CH = 42;
    int start = tid * CH;
    int end = min(start + CH, NPRI);
    int cnt = 0;
    for (int n = start; n < end; n++)
        if (sious[n] == m) cnt++;

    int inc = cnt;
    #pragma unroll
    for (int o = 1; o < 32; o <<= 1) {
        int v = __shfl_up_sync(0xffffffffu, inc, o);
        if (lane >= o) inc += v;
    }
    if (lane == 31) wsum[wid] = inc;
    __syncthreads();
    if (tid == 0) {
        int r = 0;
        #pragma unroll
        for (int w2 = 0; w2 < 8; w2++) { woff[w2] = r; r += wsum[w2]; }
        woff[8] = r;
    }
    __syncthreads();
    int excl = woff[wid] + inc - cnt;
    int k = woff[8];
    int rank = (k - 1) / 2 + 1;

    if (excl < rank && rank <= excl + cnt) {
        int need = rank - excl;
        int idx = -1;
        for (int n = start; n < end; n++)
            if (sious[n] == m && --need == 0) { idx = n; break; }
        const float* aux = g_P.aux[idx];
        float Sf = (idx < 507) ? 13.f : (idx < 2535) ? 26.f : 52.f;
        float dx = fminf(fmaxf((bx + 0.5f * bw) * Sf - aux[0], 1e-6f), 0.999999f);
        float dy = fminf(fmaxf((by + 0.5f * bh) * Sf - aux[1], 1e-6f), 0.999999f);
        g_tall[gl][0] = logf(dx / (1.0f - dx));
        g_tall[gl][1] = logf(dy / (1.0f - dy));
        g_tall[gl][2] = logf(bw * 416.0f / aux[2]);
        g_tall[gl][3] = logf(bh * 416.0f / aux[3]);
        g_cls[gl] = cls;
        g_idx[gl] = idx;
    }
}

// ---------------------------------------------------------------- loss (+final)
// grid = BB*45; each block: fixed (b, lvl, a), 256 consecutive cells
__global__ void __launch_bounds__(256) k_loss(const float* __restrict__ o0,
                                              const float* __restrict__ o1,
                                              const float* __restrict__ o2,
                                              float* __restrict__ outp) {
    __shared__ float    sacc[9];
    __shared__ int      s_n;
    __shared__ int      s_idx[LL];
    __shared__ int      s_l[LL];
    __shared__ float    s_cls[LL];
    __shared__ float    s_tall[LL][4];
    __shared__ int      swin[256];          // (l<<6)|e per local cell, -1 none
    __shared__ unsigned smask[256][3];      // class bitmask per local cell
    __shared__ bool     s_last;

    int b = blockIdx.x / BLKS_PER_B;
    int r = blockIdx.x % BLKS_PER_B;
    int tid = threadIdx.x;

    int lvl, a, c0, nc;
    if (r < 3)       { lvl = 0; a = r;            c0 = 0;               nc = 169; }
    else if (r < 12) { int q = r - 3;  lvl = 1; a = q / 3;  int bi = q % 3;
                       c0 = bi * 256; nc = (bi < 2) ? 256 : 676 - 512; }
    else             { int q = r - 12; lvl = 2; a = q / 11; int bi = q % 11;
                       c0 = bi * 256; nc = (bi < 10) ? 256 : 2704 - 2560; }

    if (tid < 9) sacc[tid] = 0.f;
    if (tid == 0) s_n = 0;
    swin[tid] = -1;
    smask[tid][0] = 0u; smask[tid][1] = 0u; smask[tid][2] = 0u;
    __syncthreads();

    if (tid < LL) {
        int gl = b * LL + tid;
        int idx = g_idx[gl];
        if (idx >= 0) {
            int p = atomicAdd(&s_n, 1);
            s_idx[p] = idx;
            s_l[p]   = tid;
            s_cls[p] = g_cls[gl];
            s_tall[p][0] = g_tall[gl][0];
            s_tall[p][1] = g_tall[gl][1];
            s_tall[p][2] = g_tall[gl][2];
            s_tall[p][3] = g_tall[gl][3];
        }
    }
    __syncthreads();
    int V = s_n;

    // mark chosen cells belonging to this block (O(V) total work)
    if (tid < V) {
        int le, ae, ce;
        decode_prior(s_idx[tid], le, ae, ce);
        if (le == lvl && ae == a && ce >= c0 && ce < c0 + nc) {
            int c = ce - c0;
            atomicMax(&swin[c], (s_l[tid] << 6) | tid);
            int ci = (int)s_cls[tid];
            atomicOr(&smask[c][ci >> 5], 1u << (ci & 31));
        }
    }
    __syncthreads();

    int cell = c0 + tid;
    bool active = tid < nc;

    int SS_ = (lvl == 0) ? 169 : (lvl == 1) ? 676 : 2704;
    const float* out = (lvl == 0) ? o0 : (lvl == 1) ? o1 : o2;
    const float* base0 = out + (size_t)b * 255 * SS_ + (size_t)a * 85 * SS_ + cell;

    bool chosen = false, supp = false;
    int we = -1;
    float objc = 0.f;

    if (active) {
        unsigned word = g_suppw[b * SUPPW_PER_B + seg_base(lvl, a) + (cell >> 5)];
        supp = (word >> (cell & 31)) & 1u;
        int win = swin[tid];
        chosen = (win >= 0);
        we = win & 63;
        if (chosen || !supp) {
            float x = base0[4 * SS_];          // coalesced obj channel
            objc = bce_term(chosen ? -x : x);
        }
    }
    if (objc != 0.f) atomicAdd(&sacc[lvl * 3 + 0], objc);

    // warp-cooperative handling of chosen priors
    unsigned cmask = __ballot_sync(0xffffffffu, chosen);
    int myl = tid & 31;
    while (cmask) {
        int src = __ffs(cmask) - 1;
        cmask &= cmask - 1;
        unsigned long long bp = __shfl_sync(0xffffffffu, (unsigned long long)base0, src);
        const float* cb = (const float*)bp;
        int cwe  = __shfl_sync(0xffffffffu, we, src);
        int cloc = __shfl_sync(0xffffffffu, tid, src);

        float csum = 0.f;
        if (myl < 4) {
            float d = cb[myl * SS_] - s_tall[cwe][myl];
            csum = d * d;
        }
        float ksum = 0.f;
        #pragma unroll
        for (int kb = 0; kb < 3; kb++) {
            int k = myl + kb * 32;
            if (k < NCLS) {
                float x = cb[(5 + k) * SS_];
                unsigned mw = smask[cloc][k >> 5];
                bool bit = (mw >> (k & 31)) & 1u;
                ksum += bce_term(bit ? -x : x);
            }
        }
        #pragma unroll
        for (int o = 16; o > 0; o >>= 1) {
            csum += __shfl_xor_sync(0xffffffffu, csum, o);
            ksum += __shfl_xor_sync(0xffffffffu, ksum, o);
        }
        if (myl == 0) {
            atomicAdd(&sacc[lvl * 3 + 1], csum);
            atomicAdd(&sacc[lvl * 3 + 2], ksum);
        }
    }

    __syncthreads();                       // all reads of supp words done
    // clear this block's supp words for the next graph replay
    if (active && (tid & 31) == 0)
        g_suppw[b * SUPPW_PER_B + seg_base(lvl, a) + (cell >> 5)] = 0u;

    if (tid < 9 && sacc[tid] != 0.f) atomicAdd(&g_acc[tid], sacc[tid]);
    __threadfence();
    __syncthreads();
    if (tid == 0)
        s_last = (atomicAdd(&g_done, 1) == (int)gridDim.x - 1);
    __syncthreads();

    if (s_last && tid == 0) {
        volatile float* acc = g_acc;
        float obj = 0.f, crd = 0.f, cl = 0.f;
        const float ss[3] = {169.f, 676.f, 2704.f};
        #pragma unroll
        for (int l = 0; l < 3; l++) {
            obj += acc[l * 3 + 0] / (48.f * ss[l]);
            crd += acc[l * 3 + 1] / (192.f * ss[l]);
            cl  += acc[l * 3 + 2] / (3840.f * ss[l]);
        }
        outp[0] = obj;
        outp[1] = crd;
        outp[2] = cl;
        #pragma unroll
        for (int i = 0; i < 9; i++) g_acc[i] = 0.f;   // reset for next replay
        g_done = 0;
    }
}

// ---------------------------------------------------------------- launch
extern "C" void kernel_launch(void* const* d_in, const int* in_sizes, int n_in,
                              void* d_out, int out_size) {
    const float *o0 = nullptr, *o1 = nullptr, *o2 = nullptr, *lab = nullptr;
    for (int i = 0; i < n_in; i++) {
        switch (in_sizes[i]) {
            case 16 * 255 * 13 * 13: o0 = (const float*)d_in[i]; break;
            case 16 * 255 * 26 * 26: o1 = (const float*)d_in[i]; break;
            case 16 * 255 * 52 * 52: o2 = (const float*)d_in[i]; break;
            case 16 * 1 * 50 * 5:    lab = (const float*)d_in[i]; break;
            default: break;
        }
    }
    if (!o0 || !o1 || !o2 || !lab) {
        o0 = (const float*)d_in[0];
        o1 = (const float*)d_in[1];
        o2 = (const float*)d_in[2];
        lab = (const float*)d_in[3];
    }

    k_targets<<<BB * LL, 256>>>(lab);
    k_loss<<<BB * BLKS_PER_B, 256>>>(o0, o1, o2, (float*)d_out);
}

// round 5
// speedup vs baseline: 1.1926x; 1.0967x over previous
#include <cuda_runtime.h>
#include <math.h>

#define NPRI  10647
#define BB    16
#define LL    50
#define NCLS  80
#define BLKS_PER_B 45      // lvl0: 3 blocks, lvl1: 9, lvl2: 33 (cell-contiguous per anchor)
#define SUPPW_PER_B 339    // 3*(6+22+85) words, segments padded per (lvl,a)
#define TT 512             // k_targets block size
#define CH 21              // ceil(10647/512)

// ---------------- compile-time priors (double math -> f32, matches numpy) ----
struct alignas(16) Priors {
    float box[NPRI][4];   // px, py, pw, ph
    float aux[NPRI][4];   // col(j), row(i), aw_pix, ah_pix
};

constexpr Priors mk_priors() {
    Priors t{};
    const int AW[3][3] = {{116, 156, 373}, {30, 62, 59}, {10, 16, 33}};
    const int AH[3][3] = {{90, 198, 326}, {61, 45, 119}, {13, 30, 23}};
    const int SSv[3] = {13, 26, 52};
    int n = 0;
    for (int l = 0; l < 3; l++) {
        int S = SSv[l];
        for (int i = 0; i < S; i++)
            for (int j = 0; j < S; j++)
                for (int a = 0; a < 3; a++) {
                    double w = AW[l][a] / 416.0;
                    double h = AH[l][a] / 416.0;
                    double cx = (j + 0.5) / (double)S;
                    double cy = (i + 0.5) / (double)S;
                    t.box[n][0] = (float)(cx - 0.5 * w);
                    t.box[n][1] = (float)(cy - 0.5 * h);
                    t.box[n][2] = (float)w;
                    t.box[n][3] = (float)h;
                    t.aux[n][0] = (float)j;
                    t.aux[n][1] = (float)i;
                    t.aux[n][2] = (float)AW[l][a];
                    t.aux[n][3] = (float)AH[l][a];
                    n++;
                }
    }
    return t;
}
__device__ constexpr Priors g_P = mk_priors();

// ---------------- compact cross-kernel state -------------------------------
__device__ int      g_idx[BB * LL];            // chosen prior per (b,label), -1 invalid
__device__ float    g_cls[BB * LL];
__device__ float    g_tall[BB * LL][4];
__device__ unsigned g_suppw[BB * SUPPW_PER_B]; // supp bitmask; cleared by k_loss each run
__device__ float    g_acc[9];                  // [lvl*3 + {obj,coord,cls}]; reset by final blk
__device__ int      g_done = 0;

// word-segment base (within one batch) for (lvl, a)
__device__ __forceinline__ int seg_base(int lvl, int a) {
    return (lvl == 0) ? a * 6 : (lvl == 1) ? 18 + a * 22 : 84 + a * 85;
}

// min(softplus(y),100) == clamped BCE term
__device__ __forceinline__ float bce_term(float y) {
    float sp = fmaxf(y, 0.0f) + __logf(1.0f + __expf(-fabsf(y)));
    return fminf(sp, 100.0f);
}

__device__ __forceinline__ float iou_f(float px, float py, float pw, float ph,
                                       float bx, float by, float bxe, float bye,
                                       float barea) {
    float ix = fmaxf(px, bx);
    float iy = fmaxf(py, by);
    float ax = fminf(__fadd_rn(px, pw), bxe);
    float ay = fminf(__fadd_rn(py, ph), bye);
    float inter = __fmul_rn(fmaxf(__fsub_rn(ax, ix), 0.0f),
                            fmaxf(__fsub_rn(ay, iy), 0.0f));
    float denom = __fsub_rn(__fadd_rn(__fmul_rn(pw, ph), barea), inter);
    return __fdiv_rn(inter, denom);
}

__device__ __forceinline__ void decode_prior(int n, int& lvl, int& a, int& cell) {
    int rl;
    if (n < 507)       { lvl = 0; rl = n; }
    else if (n < 2535) { lvl = 1; rl = n - 507; }
    else               { lvl = 2; rl = n - 2535; }
    a = rl % 3;
    cell = rl / 3;
}

// ---------------------------------------------------------------- targets
// one block per (b,label); 512 threads; no big smem (2-pass register recompute)
__global__ void __launch_bounds__(TT) k_targets(const float* __restrict__ labels) {
    __shared__ float sredf[TT / 32];
    __shared__ int   wsum[TT / 32];
    __shared__ int   woff[TT / 32 + 1];

    int gl  = blockIdx.x;
    int b   = gl / LL;
    int tid = threadIdx.x;
    int lane = tid & 31, wid = tid >> 5;
    const int NW = TT / 32;

    const float* lab = labels + (size_t)gl * 5;
    float cls = lab[0];
    if (cls < 0.0f) {
        if (tid == 0) g_idx[gl] = -1;
        return;
    }
    float bx = lab[1], by = lab[2], bw = lab[3], bh = lab[4];
    float barea = __fmul_rn(bw, bh);
    float bxe = __fadd_rn(bx, bw);
    float bye = __fadd_rn(by, bh);

    // pass 1: strided coalesced max + supp marking (no storage)
    float lmax = -1e30f;
    for (int n = tid; n < NPRI; n += TT) {
        const float4 p = *(const float4*)g_P.box[n];
        float iou = iou_f(p.x, p.y, p.z, p.w, bx, by, bxe, bye, barea);
        lmax = fmaxf(lmax, iou);
        if (iou >= 0.5f) {
            int lvl, a, cell;
            decode_prior(n, lvl, a, cell);
            atomicOr(&g_suppw[b * SUPPW_PER_B + seg_base(lvl, a) + (cell >> 5)],
                     1u << (cell & 31));
        }
    }
    #pragma unroll
    for (int o = 16; o > 0; o >>= 1)
        lmax = fmaxf(lmax, __shfl_xor_sync(0xffffffffu, lmax, o));
    if (lane == 0) sredf[wid] = lmax;
    __syncthreads();
    if (wid == 0) {
        float v = (lane < NW) ? sredf[lane] : -1e30f;
        #pragma unroll
        for (int o = 16; o > 0; o >>= 1)
            v = fmaxf(v, __shfl_xor_sync(0xffffffffu, v, o));
        if (lane == 0) sredf[0] = v;
    }
    __syncthreads();
    float m = sredf[0];

    // pass 2: ordered chunked recompute; count ties (bitwise-identical IOUs)
    int start = tid * CH;
    int end = min(start + CH, NPRI);
    int cnt = 0;
    for (int n = start; n < end; n++) {
        const float4 p = *(const float4*)g_P.box[n];
        float iou = iou_f(p.x, p.y, p.z, p.w, bx, by, bxe, bye, barea);
        if (iou == m) cnt++;
    }

    int inc = cnt;
    #pragma unroll
    for (int o = 1; o < 32; o <<= 1) {
        int v = __shfl_up_sync(0xffffffffu, inc, o);
        if (lane >= o) inc += v;
    }
    if (lane == 31) wsum[wid] = inc;
    __syncthreads();
    if (tid == 0) {
        int r = 0;
        #pragma unroll
        for (int w2 = 0; w2 < NW; w2++) { woff[w2] = r; r += wsum[w2]; }
        woff[NW] = r;
    }
    __syncthreads();
    int excl = woff[wid] + inc - cnt;
    int k = woff[NW];
    int rank = (k - 1) / 2 + 1;

    if (excl < rank && rank <= excl + cnt) {
        int need = rank - excl;
        int idx = -1;
        for (int n = start; n < end; n++) {
            const float4 p = *(const float4*)g_P.box[n];
            float iou = iou_f(p.x, p.y, p.z, p.w, bx, by, bxe, bye, barea);
            if (iou == m && --need == 0) { idx = n; break; }
        }
        const float* aux = g_P.aux[idx];
        float Sf = (idx < 507) ? 13.f : (idx < 2535) ? 26.f : 52.f;
        float dx = fminf(fmaxf((bx + 0.5f * bw) * Sf - aux[0], 1e-6f), 0.999999f);
        float dy = fminf(fmaxf((by + 0.5f * bh) * Sf - aux[1], 1e-6f), 0.999999f);
        g_tall[gl][0] = logf(dx / (1.0f - dx));
        g_tall[gl][1] = logf(dy / (1.0f - dy));
        g_tall[gl][2] = logf(bw * 416.0f / aux[2]);
        g_tall[gl][3] = logf(bh * 416.0f / aux[3]);
        g_cls[gl] = cls;
        g_idx[gl] = idx;
    }
}

// ---------------------------------------------------------------- loss (+final)
// grid = BB*45; each block: fixed (b, lvl, a), 256 consecutive cells
__global__ void __launch_bounds__(256) k_loss(const float* __restrict__ o0,
                                              const float* __restrict__ o1,
                                              const float* __restrict__ o2,
                                              float* __restrict__ outp) {
    __shared__ float    sacc[9];
    __shared__ int      s_n;
    __shared__ int      s_idx[LL];
    __shared__ float    s_cls[LL];
    __shared__ float    s_tall[LL][4];
    __shared__ int      swin[256];          // (l<<6)|e per local cell, -1 none
    __shared__ unsigned smask[256][3];      // class bitmask per local cell
    __shared__ bool     s_last;

    int b = blockIdx.x / BLKS_PER_B;
    int r = blockIdx.x % BLKS_PER_B;
    int tid = threadIdx.x;

    int lvl, a, c0, nc;
    if (r < 3)       { lvl = 0; a = r;            c0 = 0;               nc = 169; }
    else if (r < 12) { int q = r - 3;  lvl = 1; a = q / 3;  int bi = q % 3;
                       c0 = bi * 256; nc = (bi < 2) ? 256 : 676 - 512; }
    else             { int q = r - 12; lvl = 2; a = q / 11; int bi = q % 11;
                       c0 = bi * 256; nc = (bi < 10) ? 256 : 2704 - 2560; }

    if (tid < 9) sacc[tid] = 0.f;
    if (tid == 0) s_n = 0;
    swin[tid] = -1;
    smask[tid][0] = 0u; smask[tid][1] = 0u; smask[tid][2] = 0u;
    __syncthreads();

    if (tid < LL) {
        int gl = b * LL + tid;
        int idx = g_idx[gl];
        if (idx >= 0) {
            int p = atomicAdd(&s_n, 1);
            s_idx[p] = (s_idx[p], idx);   // plain store
            s_idx[p] = idx;
            s_cls[p] = g_cls[gl];
            s_tall[p][0] = g_tall[gl][0];
            s_tall[p][1] = g_tall[gl][1];
            s_tall[p][2] = g_tall[gl][2];
            s_tall[p][3] = g_tall[gl][3];
            // encode label index in winner key below via tid
            swin[0] = swin[0];            // no-op keep
            // store label order key separately:
            // reuse: we pack (label<<6)|p when marking cells; label = tid
            s_idx[p] = idx;
            ((int*)s_cls)[p] = ((int*)s_cls)[p]; // no-op
            // stash label id in high bits of s_idx? keep separate array:
        }
    }
    __syncthreads();
    int V = s_n;

    // second tiny pass to mark chosen cells with correct label-order key.
    // We need the original label index for segment_max tie-break; recover it
    // by rescanning g_idx (cheap: LL threads).
    if (tid < LL) {
        int gl = b * LL + tid;
        int idx = g_idx[gl];
        if (idx >= 0) {
            int le, ae, ce;
            decode_prior(idx, le, ae, ce);
            if (le == lvl && ae == a && ce >= c0 && ce < c0 + nc) {
                int c = ce - c0;
                // find compact slot e for this record (V<=50, linear scan ok? instead
                // store tall directly keyed by label later). Use key = (label<<8)|slot:
                // slot unknown -> mark with label; coord lookup uses per-cell label.
                atomicMax(&swin[c], tid);
                int ci = (int)g_cls[gl];
                atomicOr(&smask[c][ci >> 5], 1u << (ci & 31));
            }
        }
    }
    __syncthreads();

    int cell = c0 + tid;
    bool active = tid < nc;

    int SS_ = (lvl == 0) ? 169 : (lvl == 1) ? 676 : 2704;
    const float* out = (lvl == 0) ? o0 : (lvl == 1) ? o1 : o2;
    const float* base0 = out + (size_t)b * 255 * SS_ + (size_t)a * 85 * SS_ + cell;

    bool chosen = false;
    int wlab = -1;
    float objc = 0.f;

    if (active) {
        unsigned word = g_suppw[b * SUPPW_PER_B + seg_base(lvl, a) + (cell >> 5)];
        bool supp = (word >> (cell & 31)) & 1u;
        wlab = swin[tid];
        chosen = (wlab >= 0);
        if (chosen || !supp) {
            float x = base0[4 * SS_];          // coalesced obj channel
            objc = bce_term(chosen ? -x : x);
        }
    }
    // warp-reduce obj (whole block shares one lvl) -> 1 smem atomic per warp
    #pragma unroll
    for (int o = 16; o > 0; o >>= 1)
        objc += __shfl_xor_sync(0xffffffffu, objc, o);
    if ((tid & 31) == 0 && objc != 0.f) atomicAdd(&sacc[lvl * 3 + 0], objc);

    // warp-cooperative handling of chosen priors
    unsigned cmask = __ballot_sync(0xffffffffu, chosen);
    int myl = tid & 31;
    while (cmask) {
        int src = __ffs(cmask) - 1;
        cmask &= cmask - 1;
        unsigned long long bp = __shfl_sync(0xffffffffu, (unsigned long long)base0, src);
        const float* cb = (const float*)bp;
        int clab = __shfl_sync(0xffffffffu, wlab, src);
        int cloc = __shfl_sync(0xffffffffu, tid, src);

        float tallv = 0.f;
        if (myl < 4) tallv = g_tall[b * LL + clab][myl];

        float csum = 0.f;
        if (myl < 4) {
            float d = cb[myl * SS_] - tallv;
            csum = d * d;
        }
        float ksum = 0.f;
        #pragma unroll
        for (int kb = 0; kb < 3; kb++) {
            int k = myl + kb * 32;
            if (k < NCLS) {
                float x = cb[(5 + k) * SS_];
                unsigned mw = smask[cloc][k >> 5];
                bool bit = (mw >> (k & 31)) & 1u;
                ksum += bce_term(bit ? -x : x);
            }
        }
        #pragma unroll
        for (int o = 16; o > 0; o >>= 1) {
            csum += __shfl_xor_sync(0xffffffffu, csum, o);
            ksum += __shfl_xor_sync(0xffffffffu, ksum, o);
        }
        if (myl == 0) {
            atomicAdd(&sacc[lvl * 3 + 1], csum);
            atomicAdd(&sacc[lvl * 3 + 2], ksum);
        }
    }

    __syncthreads();                       // all reads of supp words done
    // clear this block's supp words for the next graph replay
    if (active && (tid & 31) == 0)
        g_suppw[b * SUPPW_PER_B + seg_base(lvl, a) + (cell >> 5)] = 0u;

    if (tid < 9) {
        if (sacc[tid] != 0.f) atomicAdd(&g_acc[tid], sacc[tid]);
        __threadfence();                   // release: only 9 threads pay for it
    }
    __syncthreads();
    if (tid == 0)
        s_last = (atomicAdd(&g_done, 1) == (int)gridDim.x - 1);
    __syncthreads();

    if (s_last) {
        if (tid < 9) {
            sacc[tid] = *((volatile float*)&g_acc[tid]);   // 9 parallel loads
            g_acc[tid] = 0.f;                              // reset for next replay
        }
        __syncthreads();
        if (tid == 0) {
            float obj = 0.f, crd = 0.f, cl = 0.f;
            const float ss[3] = {169.f, 676.f, 2704.f};
            #pragma unroll
            for (int l = 0; l < 3; l++) {
                obj += sacc[l * 3 + 0] / (48.f * ss[l]);
                crd += sacc[l * 3 + 1] / (192.f * ss[l]);
                cl  += sacc[l * 3 + 2] / (3840.f * ss[l]);
            }
            outp[0] = obj;
            outp[1] = crd;
            outp[2] = cl;
            g_done = 0;
        }
    }
}

// ---------------------------------------------------------------- launch
extern "C" void kernel_launch(void* const* d_in, const int* in_sizes, int n_in,
                              void* d_out, int out_size) {
    const float *o0 = nullptr, *o1 = nullptr, *o2 = nullptr, *lab = nullptr;
    for (int i = 0; i < n_in; i++) {
        switch (in_sizes[i]) {
            case 16 * 255 * 13 * 13: o0 = (const float*)d_in[i]; break;
            case 16 * 255 * 26 * 26: o1 = (const float*)d_in[i]; break;
            case 16 * 255 * 52 * 52: o2 = (const float*)d_in[i]; break;
            case 16 * 1 * 50 * 5:    lab = (const float*)d_in[i]; break;
            default: break;
        }
    }
    if (!o0 || !o1 || !o2 || !lab) {
        o0 = (const float*)d_in[0];
        o1 = (const float*)d_in[1];
        o2 = (const float*)d_in[2];
        lab = (const float*)d_in[3];
    }

    k_targets<<<BB * LL, TT>>>(lab);
    k_loss<<<BB * BLKS_PER_B, 256>>>(o0, o1, o2, (float*)d_out);
}